// round 15
// baseline (speedup 1.0000x reference)
#include <cuda_runtime.h>

#define NB     16
#define NP     65536
#define NPTS   (NB * NP)                            // 1048576 points
#define RAD_N  5
#define AZI_N  30
#define ELE_N  15
#define KSL    (ELE_N - 1)                          // 14 ele pair-slots
#define PLANE_SLOTS (AZI_N * KSL)                   // 420 slots per (b,r) plane
#define PLANE_OUTS  (AZI_N * ELE_N)                 // 450 out bins per plane
#define NPLANE (NB * RAD_N)                         // 80 planes
#define NSLOT  (NPLANE * PLANE_SLOTS)               // 33600 float4 2x2-slots

// 2x2 pair-slot histogram: slot[b][r][a][k] (a circular, k=0..13) holds
// contributions to bins (a,k),(a,k+1),(a+1%30,k),(a+1%30,k+1) in (.x,.y,.z,.w).
// INVARIANT: all-zero at entry of kernel_launch (zero-init at module load;
// fold_reset_kernel restores zeros after reading each replay).
__device__ float4 g_slots[NSLOT];

__device__ __forceinline__ void red_add4(float4* a, float x, float y, float z, float w) {
    asm volatile("red.global.add.v4.f32 [%0], {%1, %2, %3, %4};"
                 :: "l"(a), "f"(x), "f"(y), "f"(z), "f"(w) : "memory");
}

// acos on [0,1] via A&S 4.4.46 (max err ~2e-8): acos(a)=sqrt(1-a)*poly(a)
__device__ __forceinline__ float acos_poly01(float a) {
    float p = -0.0012624911f;
    p = fmaf(p, a,  0.0066700901f);
    p = fmaf(p, a, -0.0170881256f);
    p = fmaf(p, a,  0.0308918810f);
    p = fmaf(p, a, -0.0501743046f);
    p = fmaf(p, a,  0.0889789874f);
    p = fmaf(p, a, -0.2145988016f);
    p = fmaf(p, a,  1.5707963050f);
    return sqrtf(fmaxf(1.0f - a, 0.0f)) * p;
}

__device__ __forceinline__ void scatter_point(float x, float y, float z, int b) {
    float s = fmaf(x, x, fmaf(y, y, z * z));
    float rinv = rsqrtf(fmaxf(s, 1e-30f));      // MUFU.RSQ, rel err ~2^-22
    float r = s * rinv;
    if (r > 2.0f) return;   // reference culls r > DES_R

    // ---- azimuth in [0,2pi): octant-reduced atan poly ----
    float ax = fabsf(x), ay = fabsf(y);
    float mx = fmaxf(ax, ay), mn = fminf(ax, ay);
    float t = __fdividef(mn, fmaxf(mx, 1e-30f));    // [0,1]
    float u = t * t;
    float p = -0.01172120f;
    p = fmaf(p, u,  0.05265332f);
    p = fmaf(p, u, -0.11643287f);
    p = fmaf(p, u,  0.19354346f);
    p = fmaf(p, u, -0.33262347f);
    p = fmaf(p, u,  0.99997726f);
    float th = t * p;
    if (ay > ax)  th = 1.57079632679f - th;
    if (x < 0.f)  th = 3.14159265359f - th;
    if (y < 0.f)  th = 6.28318530718f - th;     // y>=0 (incl -0) unchanged
    float azi = th;

    // ---- elevation: acos(clamp(z/r)) via z*rinv ----
    float c = fminf(fmaxf(z * rinv, -1.0f), 1.0f);
    float a = fminf(fabsf(c), 1.0f);
    float ac = acos_poly01(a);
    float ele = (c >= 0.f) ? ac : (3.14159265359f - ac);

    // radial pair: closed form of ref's half-bin boundary clamps
    float vr = r * 2.5f - 0.5f;
    int jr; float wr0, wr1;
    if (vr < 0.f)        { jr = 0; wr0 = 1.f; wr1 = 0.f; }
    else if (vr >= 4.f)  { jr = 3; wr0 = 0.f; wr1 = 5.f - vr; }
    else { jr = __float2int_rd(vr); float f = vr - (float)jr; wr0 = 1.f - f; wr1 = f; }

    // azimuth pair: circular; slot sa covers bins (sa, sa+1 mod 30)
    float va = fmaf(azi, (float)(AZI_N / 6.283185307179586), -0.5f);
    int   j  = __float2int_rd(va);      // in [-1, 29]
    float fa = va - (float)j;
    int sa = (j < 0) ? (AZI_N - 1) : j;
    float wa0 = 1.f - fa, wa1 = fa;

    // elevation pair: both-end half-bin clamps
    float ve = fmaf(ele, (float)(ELE_N / 3.141592653589793), -0.5f);
    int ke; float we0, we1;
    if (ve < 0.f)         { ke = 0;  we0 = 1.f; we1 = 0.f; }
    else if (ve >= 14.f)  { ke = 13; we0 = 0.f; we1 = 1.f; }
    else { ke = __float2int_rd(ve); float f = ve - (float)ke; we0 = 1.f - f; we1 = f; }

    float p00 = wa0 * we0, p01 = wa0 * we1;
    float p10 = wa1 * we0, p11 = wa1 * we1;

    int s0 = ((b * RAD_N + jr) * AZI_N + sa) * KSL + ke;
    if (wr0 != 0.f)
        red_add4(&g_slots[s0], wr0 * p00, wr0 * p01, wr0 * p10, wr0 * p11);
    if (wr1 != 0.f)
        red_add4(&g_slots[s0 + PLANE_SLOTS], wr1 * p00, wr1 * p01, wr1 * p10, wr1 * p11);
}

// 4 points per thread via 3x float4 coalesced loads.
__global__ void __launch_bounds__(256) vox_kernel(const float* __restrict__ pts) {
    asm volatile("griddepcontrol.launch_dependents;");

    int g = blockIdx.x * 256 + threadIdx.x;     // exact multiple, no guard
    const float4* p4 = (const float4*)pts;
    float4 A = __ldg(p4 + 3 * g);
    float4 B = __ldg(p4 + 3 * g + 1);
    float4 C = __ldg(p4 + 3 * g + 2);
    int b = (g * 4) >> 16;                      // 4 pts share batch (NP%4==0)

    scatter_point(A.x, A.y, A.z, b);
    scatter_point(A.w, B.x, B.y, b);
    scatter_point(B.z, B.w, C.x, b);
    scatter_point(C.y, C.z, C.w, b);
}

// One block per (b,r) plane. Stages the plane's 420 slots in smem
// (L1-bypassed: red.global updates L2 only), re-zeros them (restoring the
// invariant for the next replay), then folds 450 output bins from smem.
__global__ void __launch_bounds__(512) fold_reset_kernel(float* __restrict__ out) {
    asm volatile("griddepcontrol.wait;");

    __shared__ float4 s[PLANE_SLOTS];
    int plane = blockIdx.x;              // rb = b*5 + r
    int tid = threadIdx.x;

    float4* gp = g_slots + plane * PLANE_SLOTS;
    if (tid < PLANE_SLOTS) {
        float4 v = __ldcg(&gp[tid]);
        s[tid] = v;
        __stcg(&gp[tid], make_float4(0.f, 0.f, 0.f, 0.f));
    }
    __syncthreads();

    if (tid < PLANE_OUTS) {
        int e   = tid % ELE_N;
        int a   = tid / ELE_N;
        int am1 = (a == 0) ? (AZI_N - 1) : (a - 1);

        float v = 0.f;
        if (e < KSL) {
            v += s[a   * KSL + e].x;
            v += s[am1 * KSL + e].z;
        }
        if (e > 0) {
            v += s[a   * KSL + e - 1].y;
            v += s[am1 * KSL + e - 1].w;
        }
        out[plane * PLANE_OUTS + tid] = v;
    }
}

extern "C" void kernel_launch(void* const* d_in, const int* in_sizes, int n_in,
                              void* d_out, int out_size) {
    const float* pts = (const float*)d_in[0];
    float* out = (float*)d_out;

    vox_kernel<<<NPTS / 4 / 256, 256>>>(pts);

    cudaLaunchConfig_t cfg = {};
    cfg.gridDim  = dim3(NPLANE, 1, 1);
    cfg.blockDim = dim3(512, 1, 1);
    cfg.dynamicSmemBytes = 0;
    cfg.stream = 0;
    cudaLaunchAttribute at[1];
    at[0].id = cudaLaunchAttributeProgrammaticStreamSerialization;
    at[0].val.programmaticStreamSerializationAllowed = 1;
    cfg.attrs = at;
    cfg.numAttrs = 1;
    cudaLaunchKernelEx(&cfg, fold_reset_kernel, out);
}

// round 16
// speedup vs baseline: 1.2686x; 1.2686x over previous
#include <cuda_runtime.h>

#define NB     16
#define NP     65536
#define NPTS   (NB * NP)                            // 1048576 points
#define RAD_N  5
#define AZI_N  30
#define ELE_N  15
#define KSL    (ELE_N - 1)                          // 14 ele pair-slots
#define PLANE_SLOTS (AZI_N * KSL)                   // 420 slots per (b,r) plane
#define PLANE_OUTS  (AZI_N * ELE_N)                 // 450 out bins per plane
#define NPLANE (NB * RAD_N)                         // 80 planes
#define NSLOT  (NPLANE * PLANE_SLOTS)               // 33600 float4 2x2-slots

// 2x2 pair-slot histogram: slot[b][r][a][k] (a circular, k=0..13) holds
// contributions to bins (a,k),(a,k+1),(a+1%30,k),(a+1%30,k+1) in (.x,.y,.z,.w).
// INVARIANT: all-zero at entry of kernel_launch (zero-init at module load;
// fold_reset_kernel restores zeros after reading each replay).
__device__ float4 g_slots[NSLOT];

__device__ __forceinline__ void red_add4(float4* a, float x, float y, float z, float w) {
    asm volatile("red.global.add.v4.f32 [%0], {%1, %2, %3, %4};"
                 :: "l"(a), "f"(x), "f"(y), "f"(z), "f"(w) : "memory");
}

__device__ __forceinline__ void scatter_point(float x, float y, float z, int b) {
    float s = fmaf(x, x, fmaf(y, y, z * z));
    float rinv = rsqrtf(fmaxf(s, 1e-30f));      // MUFU.RSQ
    float r = s * rinv;
    if (r > 2.0f) return;   // reference culls r > DES_R

    // ---- azimuth DIRECTLY in bin units (x 30/2pi baked into poly) ----
    // th = atan(t) * 4.7746483 for t in [0,1]; octant fixups in bin units.
    float ax = fabsf(x), ay = fabsf(y);
    float mx = fmaxf(ax, ay), mn = fminf(ax, ay);
    float t = __fdividef(mn, fmaxf(mx, 1e-30f));    // [0,1], MUFU-based
    float u = t * t;
    float p = -0.055964f;
    p = fmaf(p, u,  0.251395f);
    p = fmaf(p, u, -0.555922f);
    p = fmaf(p, u,  0.924098f);
    p = fmaf(p, u, -1.588168f);
    p = fmaf(p, u,  4.774540f);
    float th = t * p;                   // bins: atan in [0, 3.75]
    if (ay > ax)  th =  7.5f - th;
    if (x < 0.f)  th = 15.0f - th;
    if (y < 0.f)  th = 30.0f - th;      // [0, 30)

    // ---- elevation DIRECTLY in bin units: acos(c)*15/pi via scaled A&S poly ----
    float c = fminf(fmaxf(z * rinv, -1.0f), 1.0f);
    float a = fabsf(c);
    float w = 1.0f - a;
    float sq = w * rsqrtf(fmaxf(w, 1e-30f));    // sqrt(w), exact 0 at w=0
    float q = -0.0060279f;
    q = fmaf(q, a,  0.0318469f);
    q = fmaf(q, a, -0.0815911f);
    q = fmaf(q, a,  0.1474978f);
    q = fmaf(q, a, -0.2395650f);
    q = fmaf(q, a,  0.4248380f);
    q = fmaf(q, a, -1.0246378f);
    q = fmaf(q, a,  7.4999999f);
    float acb = sq * q;                          // acos(a) in bins, [0, 7.5]
    float ve = (c >= 0.f) ? (acb - 0.5f) : (14.5f - acb);   // ele-bins - 0.5

    // radial pair: closed form of ref's half-bin boundary clamps
    float vr = fmaf(r, 2.5f, -0.5f);
    int jr; float wr0, wr1;
    if (vr < 0.f)        { jr = 0; wr0 = 1.f; wr1 = 0.f; }
    else if (vr >= 4.f)  { jr = 3; wr0 = 0.f; wr1 = 5.f - vr; }
    else { jr = __float2int_rd(vr); float f = vr - (float)jr; wr0 = 1.f - f; wr1 = f; }

    // azimuth pair: circular; slot sa covers bins (sa, sa+1 mod 30)
    float va = th - 0.5f;
    int   j  = __float2int_rd(va);      // in [-1, 29]
    float fa = va - (float)j;
    int sa = (j < 0) ? (AZI_N - 1) : j;
    float wa0 = 1.f - fa, wa1 = fa;

    // elevation pair: both-end half-bin clamps
    int ke; float we0, we1;
    if (ve < 0.f)         { ke = 0;  we0 = 1.f; we1 = 0.f; }
    else if (ve >= 14.f)  { ke = 13; we0 = 0.f; we1 = 1.f; }
    else { ke = __float2int_rd(ve); float f = ve - (float)ke; we0 = 1.f - f; we1 = f; }

    float p00 = wa0 * we0, p01 = wa0 * we1;
    float p10 = wa1 * we0, p11 = wa1 * we1;

    int s0 = ((b * RAD_N + jr) * AZI_N + sa) * KSL + ke;
    if (wr0 != 0.f)
        red_add4(&g_slots[s0], wr0 * p00, wr0 * p01, wr0 * p10, wr0 * p11);
    if (wr1 != 0.f)
        red_add4(&g_slots[s0 + PLANE_SLOTS], wr1 * p00, wr1 * p01, wr1 * p10, wr1 * p11);
}

// 4 points per thread via 3x float4 coalesced loads.
__global__ void __launch_bounds__(256) vox_kernel(const float* __restrict__ pts) {
    asm volatile("griddepcontrol.launch_dependents;");

    int g = blockIdx.x * 256 + threadIdx.x;     // exact multiple, no guard
    const float4* p4 = (const float4*)pts;
    float4 A = __ldg(p4 + 3 * g);
    float4 B = __ldg(p4 + 3 * g + 1);
    float4 C = __ldg(p4 + 3 * g + 2);
    int b = (g * 4) >> 16;                      // 4 pts share batch (NP%4==0)

    scatter_point(A.x, A.y, A.z, b);
    scatter_point(A.w, B.x, B.y, b);
    scatter_point(B.z, B.w, C.x, b);
    scatter_point(C.y, C.z, C.w, b);
}

// One block per (b,r) plane. Stages the plane's 420 slots in smem
// (L1-bypassed: red.global updates L2 only), re-zeros them (restoring the
// invariant for the next replay), then folds 450 output bins from smem.
__global__ void __launch_bounds__(512) fold_reset_kernel(float* __restrict__ out) {
    asm volatile("griddepcontrol.wait;");

    __shared__ float4 s[PLANE_SLOTS];
    int plane = blockIdx.x;              // rb = b*5 + r
    int tid = threadIdx.x;

    float4* gp = g_slots + plane * PLANE_SLOTS;
    if (tid < PLANE_SLOTS) {
        float4 v = __ldcg(&gp[tid]);
        s[tid] = v;
        __stcg(&gp[tid], make_float4(0.f, 0.f, 0.f, 0.f));
    }
    __syncthreads();

    if (tid < PLANE_OUTS) {
        int e   = tid % ELE_N;
        int a   = tid / ELE_N;
        int am1 = (a == 0) ? (AZI_N - 1) : (a - 1);

        float v = 0.f;
        if (e < KSL) {
            v += s[a   * KSL + e].x;
            v += s[am1 * KSL + e].z;
        }
        if (e > 0) {
            v += s[a   * KSL + e - 1].y;
            v += s[am1 * KSL + e - 1].w;
        }
        out[plane * PLANE_OUTS + tid] = v;
    }
}

extern "C" void kernel_launch(void* const* d_in, const int* in_sizes, int n_in,
                              void* d_out, int out_size) {
    const float* pts = (const float*)d_in[0];
    float* out = (float*)d_out;

    vox_kernel<<<NPTS / 4 / 256, 256>>>(pts);

    cudaLaunchConfig_t cfg = {};
    cfg.gridDim  = dim3(NPLANE, 1, 1);
    cfg.blockDim = dim3(512, 1, 1);
    cfg.dynamicSmemBytes = 0;
    cfg.stream = 0;
    cudaLaunchAttribute at[1];
    at[0].id = cudaLaunchAttributeProgrammaticStreamSerialization;
    at[0].val.programmaticStreamSerializationAllowed = 1;
    cfg.attrs = at;
    cfg.numAttrs = 1;
    cudaLaunchKernelEx(&cfg, fold_reset_kernel, out);
}